// round 11
// baseline (speedup 1.0000x reference)
#include <cuda_runtime.h>

// LengthRegulator:
// ys[b, f, :] = xs[b, i, :] where cum[b,i-1] <= f < cum[b,i], else 0.
//
// Kernel A: per-batch shuffle scan of ds -> g_cum (8x512, inclusive).
// Kernel B: 256-thread blocks, 32 frames each. Prologue reads g_cum,
// scatters frame->row map into shared. Copy: warp-per-4-frames with
// run-length source-load elimination (only re-load on row change).

#define BATCH   8
#define TIN     512
#define TOUT    4096
#define DIM4    96                  // 384/4 float4 per row
#define FPB     32                  // frames per block
#define BTHR    256                 // 8 warps
#define FPW     4                   // frames per warp

__device__ int    g_cum[BATCH * TIN];
__device__ float4 g_zero[DIM4];     // stays zero (never written)

__global__ __launch_bounds__(512)
void lr_scan(const int* __restrict__ ds)
{
    __shared__ int s_wsum[16];

    const int b    = blockIdx.x;
    const int tid  = threadIdx.x;
    const int lane = tid & 31;
    const int wid  = tid >> 5;

    int v = ds[b * TIN + tid];
#pragma unroll
    for (int off = 1; off < 32; off <<= 1) {
        int n = __shfl_up_sync(0xffffffffu, v, off);
        if (lane >= off) v += n;
    }
    if (lane == 31) s_wsum[wid] = v;
    __syncthreads();
    if (wid == 0 && lane < 16) {
        int w = s_wsum[lane];
#pragma unroll
        for (int off = 1; off < 16; off <<= 1) {
            int n = __shfl_up_sync(0x0000ffffu, w, off);
            if (lane >= off) w += n;
        }
        s_wsum[lane] = w;
    }
    __syncthreads();
    g_cum[b * TIN + tid] = v + (wid > 0 ? s_wsum[wid - 1] : 0);
}

__global__ __launch_bounds__(BTHR, 8)
void lr_copy(const float4* __restrict__ xs,
             float4* __restrict__ out)
{
    __shared__ int s_map[FPB];

    const int b      = blockIdx.x;
    const int frame0 = blockIdx.y * FPB;
    const int tid    = threadIdx.x;
    const int lane   = tid & 31;
    const int wid    = tid >> 5;

    if (tid < FPB) s_map[tid] = -1;
    __syncthreads();

    // scatter: each thread covers rows tid and tid+256
    const int* cumb = g_cum + b * TIN;
#pragma unroll
    for (int h = 0; h < 2; h++) {
        const int r    = tid + h * BTHR;
        const int cum  = cumb[r];
        const int left = (r > 0) ? cumb[r - 1] : 0;
        int lo = left < frame0 ? frame0 : left;
        int hi = cum  > frame0 + FPB ? frame0 + FPB : cum;
        for (int f = lo; f < hi; f++)
            s_map[f - frame0] = r;
    }
    __syncthreads();

    // copy: warp w owns frames [frame0 + w*FPW, +FPW)
    const float4* __restrict__ xsb = xs + (size_t)b * TIN * DIM4;
    const int fbase = wid * FPW;
    float4* __restrict__ o =
        out + (size_t)(b * TOUT + frame0 + fbase) * DIM4 + lane;

    int prev_row = -2;
    float4 a0, a1, a2;
#pragma unroll
    for (int k = 0; k < FPW; k++) {
        const int row = s_map[fbase + k];          // warp-uniform
        if (row != prev_row) {                     // uniform branch
            const float4* p = (row >= 0) ? (xsb + row * DIM4) : g_zero;
            a0 = p[lane];
            a1 = p[lane + 32];
            a2 = p[lane + 64];
            prev_row = row;
        }
        o[k * DIM4]      = a0;
        o[k * DIM4 + 32] = a1;
        o[k * DIM4 + 64] = a2;
    }
}

extern "C" void kernel_launch(void* const* d_in, const int* in_sizes, int n_in,
                              void* d_out, int out_size)
{
    const float* xs = (const float*)d_in[0];
    const int*   ds = (const int*)d_in[1];
    float*       out = (float*)d_out;

    lr_scan<<<BATCH, 512>>>(ds);

    dim3 grid(BATCH, TOUT / FPB);   // 8 x 128 = 1024 blocks, single wave @8/SM
    lr_copy<<<grid, BTHR>>>((const float4*)xs, (float4*)out);
}